// round 16
// baseline (speedup 1.0000x reference)
#include <cuda_runtime.h>
#include <cuda_fp16.h>
#include <cstdint>

#define LPn 4096
#define LHn 4096
#define Dn 300
#define Hn 512
#define NSPL 16
#define DP 304   // Dn padded to x8
#define CP 608   // 2*Dn padded to x8

// ---------------- scratch (device globals; no allocation allowed) ----------
__device__ __half g_t1h[(LPn + LHn) * Hn];
__device__ __half g_fah[(LPn + LHn) * Hn];
__device__ __half g_cath[(LPn + LHn) * CP];
__device__ __half g_G1h[Dn * Hn];
__device__ __half g_G2h[Dn * Hn];
__device__ __half g_wa1[Hn * DP];
__device__ __half g_wa2[Hn * Hn];
__device__ __half g_wc1[Hn * CP];
__device__ __half g_wc2[Hn * Hn];
__device__ float g_part[NSPL * Dn * Hn];
__device__ float g_part2[NSPL * Dn * Hn];
__device__ float g_eik[LPn];
__device__ float g_ekj[LHn];
__device__ float g_v[2 * Hn];
__device__ float g_y1[Hn];
__device__ float g_y2[Hn];

// ---------------- helpers ---------------------------------------------------
__device__ __forceinline__ void cpa16(uint32_t saddr, const void* g, uint32_t vb) {
    asm volatile("cp.async.cg.shared.global [%0], [%1], 16, %2;"
                 ::"r"(saddr), "l"(g), "r"(vb));
}
#define CP_COMMIT() asm volatile("cp.async.commit_group;" ::: "memory")
#define CP_WAIT1() asm volatile("cp.async.wait_group 1;" ::: "memory")

__device__ __forceinline__ void mma16(float* c, const uint32_t* a, uint32_t b0, uint32_t b1) {
    asm volatile(
        "mma.sync.aligned.m16n8k16.row.col.f32.f16.f16.f32 "
        "{%0,%1,%2,%3}, {%4,%5,%6,%7}, {%8,%9}, {%0,%1,%2,%3};"
        : "+f"(c[0]), "+f"(c[1]), "+f"(c[2]), "+f"(c[3])
        : "r"(a[0]), "r"(a[1]), "r"(a[2]), "r"(a[3]), "r"(b0), "r"(b1));
}
__device__ __forceinline__ void ldm4(uint32_t* r, uint32_t addr) {
    asm volatile("ldmatrix.sync.aligned.m8n8.x4.shared.b16 {%0,%1,%2,%3}, [%4];"
                 : "=r"(r[0]), "=r"(r[1]), "=r"(r[2]), "=r"(r[3]) : "r"(addr));
}
__device__ __forceinline__ void ldm4t(uint32_t* r, uint32_t addr) {
    asm volatile("ldmatrix.sync.aligned.m8n8.x4.trans.shared.b16 {%0,%1,%2,%3}, [%4];"
                 : "=r"(r[0]), "=r"(r[1]), "=r"(r[2]), "=r"(r[3]) : "r"(addr));
}

// direct: src half [rows][ld]; chunk [k0,k0+64) -> smem [r][k] stride 72 halves
__device__ __forceinline__ void loadDirH(const __half* __restrict__ src, int ld,
                                         int row0, int rlim, int k0, int kend,
                                         uint32_t saddr) {
    int t = threadIdx.x;
    int r = t >> 1, kb = (t & 1) * 32;
    int gr = row0 + r;
    bool rok = gr < rlim;
    const __half* p = src + (size_t)(rok ? gr : row0) * ld + k0 + kb;
    uint32_t sa = saddr + (uint32_t)(r * 72 + kb) * 2;
#pragma unroll
    for (int j = 0; j < 4; j++) {
        int gk = k0 + kb + j * 8;
        uint32_t vb = (rok && gk + 8 <= kend) ? 16u : 0u;
        cpa16(sa + j * 16, p + j * 8, vb);
    }
}

// trans: src half [Ktot][ld]; k rows [k0,k0+64), cols [c0,c0+128) -> smem [k][c] stride 136
__device__ __forceinline__ void loadTransH(const __half* __restrict__ src, int ld,
                                           int c0, int clim, int k0, int kend,
                                           uint32_t saddr) {
    int t = threadIdx.x;
    int k = t >> 2;
    int gk = k0 + k;
    bool kok = gk < kend;
    const __half* p = src + (size_t)(kok ? gk : k0) * ld + c0;
    uint32_t sa = saddr + (uint32_t)(k * 136) * 2;
#pragma unroll
    for (int j = 0; j < 4; j++) {
        int moff = ((t & 3) * 4 + j) * 8;
        int gm = c0 + moff;
        uint32_t vb = (kok && gm + 8 <= clim) ? 16u : 0u;
        cpa16(sa + (uint32_t)moff * 2, p + moff, vb);
    }
}

// ---------------- fp16 mma GEMM, cp.async 3-stage, BK=64 -------------------
// AT: A[m,k]=src[k*lda+m]. BT: B[k,n]=src[k*ldb+n]; else B = W-form [N,K].
// EPI: 0 plain; 1 bias+relu; 2 rowscale fp32 store + half copy into ph (+Dn);
//      3 store + atomic row sums p1 / col sums p2; 4 bias+relu, atomic col
//      sums into p1 (+Hn for h-rows), no store.
template <bool AT, bool BT, int EPI, bool OH, bool SPLITK>
__global__ void __launch_bounds__(256, 2)
hgemm(const __half* __restrict__ A, int lda,
      const __half* __restrict__ B, int ldb,
      const float* __restrict__ aux,
      void* __restrict__ Cv, int ldc,
      int M, int N, int K, int Ksub, int aclim,
      float* __restrict__ p1, float* __restrict__ p2,
      __half* __restrict__ ph) {
    constexpr int AWH = AT ? 64 * 136 : 128 * 72;
    constexpr int BWH = BT ? 64 * 136 : 128 * 72;
    constexpr int STH = AWH + BWH;
    extern __shared__ __half smh[];
    const uint32_t sbase = (uint32_t)__cvta_generic_to_shared(smh);

    const int tid = threadIdx.x, wid = tid >> 5, lane = tid & 31;
    const int gid = lane >> 2, tig = lane & 3;
    const int wm = wid >> 1, wn = wid & 1;
    const int bm = blockIdx.y * 128, bn = blockIdx.x * 128;

    int k_off = 0, Kloc = K;
    if (SPLITK) {
        k_off = blockIdx.z * Ksub;
        Kloc = Ksub;
        Cv = (void*)((float*)Cv + (size_t)blockIdx.z * M * ldc);
    }
    const int kend = k_off + Kloc;
    const int NC = (Kloc + 63) / 64;

    float acc[2][8][4];
#pragma unroll
    for (int i = 0; i < 2; i++)
#pragma unroll
        for (int j = 0; j < 8; j++)
#pragma unroll
            for (int q = 0; q < 4; q++) acc[i][j][q] = 0.f;

    uint32_t a_off;
    if (AT) {
        int krow = ((lane >> 4) << 3) + (lane & 7);
        int moff = ((lane >> 3) & 1) * 8;
        a_off = (uint32_t)(krow * 136 + wm * 32 + moff) * 2;
    } else {
        a_off = (uint32_t)((wm * 32 + (lane & 15)) * 72 + (lane >> 4) * 8) * 2;
    }
    uint32_t b_off;
    if (BT) {
        int krow = ((lane >> 3) & 1) * 8 + (lane & 7);
        int noff = (lane >> 4) * 8;
        b_off = (uint32_t)AWH * 2 + (uint32_t)(krow * 136 + wn * 64 + noff) * 2;
    } else {
        b_off = (uint32_t)AWH * 2 +
                (uint32_t)((wn * 64 + ((lane >> 4) << 3) + (lane & 7)) * 72 +
                           ((lane >> 3) & 1) * 8) * 2;
    }

#pragma unroll
    for (int pc = 0; pc < 2; pc++) {
        uint32_t sA = sbase + (uint32_t)(pc * STH) * 2;
        uint32_t sB = sA + (uint32_t)AWH * 2;
        int k0 = k_off + pc * 64;
        if (AT) loadTransH(A, lda, bm, aclim, k0, kend, sA);
        else    loadDirH(A, lda, bm, M, k0, kend, sA);
        if (BT) loadTransH(B, ldb, bn, N, k0, kend, sB);
        else    loadDirH(B, ldb, bn, N, k0, kend, sB);
        CP_COMMIT();
    }

    for (int kc = 0; kc < NC; kc++) {
        CP_WAIT1();
        __syncthreads();
        if (kc + 2 < NC) {
            int st = (kc + 2) % 3;
            int k0 = k_off + (kc + 2) * 64;
            uint32_t sA = sbase + (uint32_t)(st * STH) * 2;
            uint32_t sB = sA + (uint32_t)AWH * 2;
            if (AT) loadTransH(A, lda, bm, aclim, k0, kend, sA);
            else    loadDirH(A, lda, bm, M, k0, kend, sA);
            if (BT) loadTransH(B, ldb, bn, N, k0, kend, sB);
            else    loadDirH(B, ldb, bn, N, k0, kend, sB);
        }
        CP_COMMIT();

        const uint32_t stoff = (uint32_t)((kc % 3) * STH) * 2;
#pragma unroll
        for (int kk = 0; kk < 4; kk++) {
            uint32_t a[2][4];
            if (AT) {
                uint32_t ab = sbase + stoff + a_off + (uint32_t)(kk * 16 * 136) * 2;
                ldm4t(a[0], ab);
                ldm4t(a[1], ab + 16 * 2);
            } else {
                uint32_t ab = sbase + stoff + a_off + (uint32_t)(kk * 16) * 2;
                ldm4(a[0], ab);
                ldm4(a[1], ab + (uint32_t)(16 * 72) * 2);
            }
            uint32_t b[8][2];
#pragma unroll
            for (int nj = 0; nj < 4; nj++) {
                uint32_t r[4];
                if (BT) ldm4t(r, sbase + stoff + b_off + (uint32_t)(kk * 16 * 136 + nj * 16) * 2);
                else    ldm4 (r, sbase + stoff + b_off + (uint32_t)(nj * 16 * 72 + kk * 16) * 2);
                b[2 * nj][0] = r[0]; b[2 * nj][1] = r[1];
                b[2 * nj + 1][0] = r[2]; b[2 * nj + 1][1] = r[3];
            }
#pragma unroll
            for (int ni = 0; ni < 8; ni++) {
                mma16(acc[0][ni], a[0], b[ni][0], b[ni][1]);
                mma16(acc[1][ni], a[1], b[ni][0], b[ni][1]);
            }
        }
    }

    // ---------------- epilogue ----------------
    float csum0[8], csum1[8];
    if (EPI == 3 || EPI == 4) {
#pragma unroll
        for (int ni = 0; ni < 8; ni++) { csum0[ni] = 0.f; csum1[ni] = 0.f; }
    }
#pragma unroll
    for (int mi = 0; mi < 2; mi++) {
        int r0 = bm + wm * 32 + mi * 16 + gid;
        float s0 = 1.f, s1 = 1.f;
        if (EPI == 2) {
            if (r0 < M) s0 = 1.f / aux[r0];
            if (r0 + 8 < M) s1 = 1.f / aux[r0 + 8];
        }
        float rs0 = 0.f, rs1 = 0.f;
#pragma unroll
        for (int ni = 0; ni < 8; ni++) {
            int col = bn + wn * 64 + ni * 8 + tig * 2;
            if (col >= N) continue;
            float v0 = acc[mi][ni][0], v1 = acc[mi][ni][1];
            float v2 = acc[mi][ni][2], v3 = acc[mi][ni][3];
            if (EPI == 1 || EPI == 4) {
                float bi0 = aux[col];
                float bi1 = (col + 1 < N) ? aux[col + 1] : 0.f;
                v0 = fmaxf(v0 + bi0, 0.f); v1 = fmaxf(v1 + bi1, 0.f);
                v2 = fmaxf(v2 + bi0, 0.f); v3 = fmaxf(v3 + bi1, 0.f);
            }
            if (EPI == 2) { v0 *= s0; v1 *= s0; v2 *= s1; v3 *= s1; }
            if (EPI != 4) {
                if (OH) {
                    __half* C = (__half*)Cv;
                    if (col + 1 < N) {
                        if (r0 < M) *(__half2*)(C + (size_t)r0 * ldc + col) = __floats2half2_rn(v0, v1);
                        if (r0 + 8 < M) *(__half2*)(C + (size_t)(r0 + 8) * ldc + col) = __floats2half2_rn(v2, v3);
                    } else {
                        if (r0 < M) C[(size_t)r0 * ldc + col] = __float2half_rn(v0);
                        if (r0 + 8 < M) C[(size_t)(r0 + 8) * ldc + col] = __float2half_rn(v2);
                    }
                } else {
                    float* C = (float*)Cv;
                    if (col + 1 < N) {
                        if (r0 < M) *(float2*)(C + (size_t)r0 * ldc + col) = make_float2(v0, v1);
                        if (r0 + 8 < M) *(float2*)(C + (size_t)(r0 + 8) * ldc + col) = make_float2(v2, v3);
                    } else {
                        if (r0 < M) C[(size_t)r0 * ldc + col] = v0;
                        if (r0 + 8 < M) C[(size_t)(r0 + 8) * ldc + col] = v2;
                    }
                }
            }
            if (EPI == 2) {
                if (r0 < M) *(__half2*)(ph + (size_t)r0 * CP + Dn + col) = __floats2half2_rn(v0, v1);
                if (r0 + 8 < M) *(__half2*)(ph + (size_t)(r0 + 8) * CP + Dn + col) = __floats2half2_rn(v2, v3);
            }
            if (EPI == 3) {
                rs0 += v0 + v1; rs1 += v2 + v3;
                csum0[ni] += v0 + v2; csum1[ni] += v1 + v3;
            }
            if (EPI == 4) {
                csum0[ni] += v0 + v2; csum1[ni] += v1 + v3;
            }
        }
        if (EPI == 3) {
            rs0 += __shfl_xor_sync(0xffffffffu, rs0, 1);
            rs0 += __shfl_xor_sync(0xffffffffu, rs0, 2);
            rs1 += __shfl_xor_sync(0xffffffffu, rs1, 1);
            rs1 += __shfl_xor_sync(0xffffffffu, rs1, 2);
            if (tig == 0) {
                atomicAdd(&p1[r0], rs0);
                atomicAdd(&p1[r0 + 8], rs1);
            }
        }
    }
    if (EPI == 3 || EPI == 4) {
        float* cbase = (EPI == 3) ? p2 : (p1 + ((bm >= LPn) ? Hn : 0));
#pragma unroll
        for (int ni = 0; ni < 8; ni++) {
            int col = bn + wn * 64 + ni * 8 + tig * 2;
            if (col >= N) continue;
            float c0 = csum0[ni], c1 = csum1[ni];
            c0 += __shfl_xor_sync(0xffffffffu, c0, 4);
            c0 += __shfl_xor_sync(0xffffffffu, c0, 8);
            c0 += __shfl_xor_sync(0xffffffffu, c0, 16);
            c1 += __shfl_xor_sync(0xffffffffu, c1, 4);
            c1 += __shfl_xor_sync(0xffffffffu, c1, 8);
            c1 += __shfl_xor_sync(0xffffffffu, c1, 16);
            if (gid == 0) {
                atomicAdd(&cbase[col], c0);
                atomicAdd(&cbase[col + 1], c1);
            }
        }
    }
}

// ---------------- merged prep kernel ---------------------------------------
__device__ __forceinline__ void cvt8(const float* p, int sld_valid, __half* dst) {
    __half h[8];
#pragma unroll
    for (int i = 0; i < 8; i++) h[i] = __float2half_rn((i < sld_valid) ? p[i] : 0.f);
    *(uint4*)dst = *(uint4*)h;
}

__global__ void prep_k(const int* __restrict__ p_idx, const int* __restrict__ h_idx,
                       const float* __restrict__ emb,
                       const float* __restrict__ W_a1, const float* __restrict__ W_a2,
                       const float* __restrict__ W_c1, const float* __restrict__ W_c2) {
    int b = blockIdx.x, tid = threadIdx.x;
    if (b < 1216) {  // gather: 8192 rows * 38 groups -> cath cols [0,304) + tail zero
        int t = b * 256 + tid;
        int r = t / (DP / 8), g = t - r * (DP / 8);
        int base = g * 8;
        int ix = (r < LPn) ? p_idx[r] : h_idx[r - LPn];
        const float* src = emb + (size_t)ix * Dn;
        __half h[8];
#pragma unroll
        for (int i = 0; i < 8; i++) {
            int c = base + i;
            h[i] = __float2half_rn((c < Dn) ? src[c] : 0.f);
        }
        *(uint4*)(g_cath + (size_t)r * CP + base) = *(uint4*)h;
        if (g == 0) {
            uint4 z = make_uint4(0u, 0u, 0u, 0u);
            *(uint4*)(g_cath + (size_t)r * CP + 2 * Dn) = z;
        }
    } else if (b < 1292) {  // wa1
        int t = (b - 1216) * 256 + tid;
        int r = t / (DP / 8), g = t - r * (DP / 8);
        int base = g * 8;
        cvt8(W_a1 + (size_t)r * Dn + base, Dn - base, g_wa1 + (size_t)r * DP + base);
    } else if (b < 1420) {  // wa2
        int t = (b - 1292) * 256 + tid;
        int base = (t % (Hn / 8)) * 8, r = t / (Hn / 8);
        cvt8(W_a2 + (size_t)r * Hn + base, 8, g_wa2 + (size_t)r * Hn + base);
    } else if (b < 1572) {  // wc1
        int t = (b - 1420) * 256 + tid;
        int r = t / (CP / 8), g = t - r * (CP / 8);
        int base = g * 8;
        cvt8(W_c1 + (size_t)r * 2 * Dn + base, 2 * Dn - base, g_wc1 + (size_t)r * CP + base);
    } else if (b < 1700) {  // wc2
        int t = (b - 1572) * 256 + tid;
        int base = (t % (Hn / 8)) * 8, r = t / (Hn / 8);
        cvt8(W_c2 + (size_t)r * Hn + base, 8, g_wc2 + (size_t)r * Hn + base);
    } else {  // zero
        int t = (b - 1700) * 256 + tid;
        g_eik[t] = 0.f;
        g_ekj[t] = 0.f;
        if (t < 2 * Hn) g_v[t] = 0.f;
    }
}

// merged reduce: section 0 -> G1h from part, section 1 -> G2h from part2
__global__ void reduce2_h(const float* __restrict__ part, const float* __restrict__ part2,
                          __half* __restrict__ o1, __half* __restrict__ o2, int MN) {
    int t = blockIdx.x * blockDim.x + threadIdx.x;
    int half = MN / 4;
    if (t >= 2 * half) return;
    const float* p = (t < half) ? part : part2;
    __half* o = (t < half) ? o1 : o2;
    int ti = (t < half) ? t : t - half;
    float4 s = make_float4(0.f, 0.f, 0.f, 0.f);
#pragma unroll
    for (int z = 0; z < NSPL; z++) {
        float4 v = ((const float4*)(p + (size_t)z * MN))[ti];
        s.x += v.x; s.y += v.y; s.z += v.z; s.w += v.w;
    }
    ((__half2*)o)[ti * 2] = __floats2half2_rn(s.x, s.y);
    ((__half2*)o)[ti * 2 + 1] = __floats2half2_rn(s.z, s.w);
}

// ---------------- parallel final head --------------------------------------
__global__ void fin_k(const float* __restrict__ W, const float* __restrict__ b,
                      const float* __restrict__ x, float* __restrict__ y,
                      float* __restrict__ outv, int Kd) {
    int o = blockIdx.x, tid = threadIdx.x, wid = tid >> 5, lane = tid & 31;
    const float4* Wr = (const float4*)(W + (size_t)o * Kd);
    const float4* xr = (const float4*)x;
    float s = 0.f;
    for (int i = tid; i < Kd / 4; i += 256) {
        float4 w = Wr[i], xv = xr[i];
        s += w.x * xv.x + w.y * xv.y + w.z * xv.z + w.w * xv.w;
    }
#pragma unroll
    for (int off = 16; off; off >>= 1) s += __shfl_xor_sync(0xffffffffu, s, off);
    __shared__ float ws[8];
    if (lane == 0) ws[wid] = s;
    __syncthreads();
    if (tid == 0) {
        float t = 0.f;
#pragma unroll
        for (int w = 0; w < 8; w++) t += ws[w];
        y[o] = fmaxf(t + b[o], 0.f);
    }
    if (outv && tid < 2) outv[o * 2 + tid] = x[o * 2 + tid];
}

__global__ void fin3_k(const float* __restrict__ W3, const float* __restrict__ b3,
                       const float* __restrict__ y2, float* __restrict__ outy) {
    __shared__ float z[3];
    int tid = threadIdx.x, c = tid >> 5, lane = tid & 31;
    if (c < 3) {
        float s = 0.f;
        for (int k = lane; k < Hn; k += 32) s += W3[c * Hn + k] * y2[k];
#pragma unroll
        for (int off = 16; off; off >>= 1) s += __shfl_xor_sync(0xffffffffu, s, off);
        if (lane == 0) z[c] = s + b3[c];
    }
    __syncthreads();
    if (tid == 0) {
        float mx = fmaxf(z[0], fmaxf(z[1], z[2]));
        float e0 = expf(z[0] - mx), e1 = expf(z[1] - mx), e2 = expf(z[2] - mx);
        float se = e0 + e1 + e2;
        outy[0] = e0 / se; outy[1] = e1 / se; outy[2] = e2 / se;
    }
}

// ---------------- launch --------------------------------------------------
#define SM_DD (3 * (128 * 72 + 128 * 72) * 2)
#define SM_TD (3 * (64 * 136 + 128 * 72) * 2)
#define SM_DT (3 * (128 * 72 + 64 * 136) * 2)
#define SM_TT (3 * (64 * 136 + 64 * 136) * 2)

extern "C" void kernel_launch(void* const* d_in, const int* in_sizes, int n_in,
                              void* d_out, int out_size) {
    const int*   p_idx = (const int*)d_in[0];
    const int*   h_idx = (const int*)d_in[1];
    const float* emb   = (const float*)d_in[2];
    const float* W_a1  = (const float*)d_in[3];
    const float* b_a1  = (const float*)d_in[4];
    const float* W_a2  = (const float*)d_in[5];
    const float* b_a2  = (const float*)d_in[6];
    const float* W_c1  = (const float*)d_in[7];
    const float* b_c1  = (const float*)d_in[8];
    const float* W_c2  = (const float*)d_in[9];
    const float* b_c2  = (const float*)d_in[10];
    const float* W_g1  = (const float*)d_in[11];
    const float* b_g1  = (const float*)d_in[12];
    const float* W_g2  = (const float*)d_in[13];
    const float* b_g2  = (const float*)d_in[14];
    const float* W_g3  = (const float*)d_in[15];
    const float* b_g3  = (const float*)d_in[16];

    float* out      = (float*)d_out;
    float* outE     = out;
    float* outBeta  = outE + (size_t)LPn * LHn;
    float* outAlpha = outBeta + (size_t)LPn * Dn;
    float* outV     = outAlpha + (size_t)LHn * Dn;
    float* outY     = outV + 2 * Hn;

    __half *t1h, *fah, *cath, *G1h, *G2h;
    __half *wa1, *wa2, *wc1, *wc2;
    float *part, *part2, *eik, *ekj, *v, *y1, *y2;
    cudaGetSymbolAddress((void**)&t1h, g_t1h);
    cudaGetSymbolAddress((void**)&fah, g_fah);
    cudaGetSymbolAddress((void**)&cath, g_cath);
    cudaGetSymbolAddress((void**)&G1h, g_G1h);
    cudaGetSymbolAddress((void**)&G2h, g_G2h);
    cudaGetSymbolAddress((void**)&wa1, g_wa1);
    cudaGetSymbolAddress((void**)&wa2, g_wa2);
    cudaGetSymbolAddress((void**)&wc1, g_wc1);
    cudaGetSymbolAddress((void**)&wc2, g_wc2);
    cudaGetSymbolAddress((void**)&part, g_part);
    cudaGetSymbolAddress((void**)&part2, g_part2);
    cudaGetSymbolAddress((void**)&eik, g_eik);
    cudaGetSymbolAddress((void**)&ekj, g_ekj);
    cudaGetSymbolAddress((void**)&v, g_v);
    cudaGetSymbolAddress((void**)&y1, g_y1);
    cudaGetSymbolAddress((void**)&y2, g_y2);

    cudaFuncSetAttribute(hgemm<false, false, 1, true, false>,  cudaFuncAttributeMaxDynamicSharedMemorySize, SM_DD);
    cudaFuncSetAttribute(hgemm<true, false, 0, false, true>,   cudaFuncAttributeMaxDynamicSharedMemorySize, SM_TD);
    cudaFuncSetAttribute(hgemm<true, true, 0, false, true>,    cudaFuncAttributeMaxDynamicSharedMemorySize, SM_TT);
    cudaFuncSetAttribute(hgemm<false, true, 3, false, false>,  cudaFuncAttributeMaxDynamicSharedMemorySize, SM_DT);
    cudaFuncSetAttribute(hgemm<false, false, 2, false, false>, cudaFuncAttributeMaxDynamicSharedMemorySize, SM_DD);
    cudaFuncSetAttribute(hgemm<true, false, 2, false, false>,  cudaFuncAttributeMaxDynamicSharedMemorySize, SM_TD);
    cudaFuncSetAttribute(hgemm<false, false, 4, false, false>, cudaFuncAttributeMaxDynamicSharedMemorySize, SM_DD);

    const int TB = 256;
    const int MT = LPn + LHn;  // 8192
    const __half* fhR = fah + (size_t)LPn * Hn;  // reshape(fh,[H,LH]) = [512][4096]

    // (1) merged prep: gather -> cath + weight converts + zeroing
    prep_k<<<1716, TB>>>(p_idx, h_idx, emb, W_a1, W_a2, W_c1, W_c2);

    // (2,3) attend (merged p|h); A read from cath cols [0,304)
    hgemm<false, false, 1, true, false><<<dim3(Hn / 128, MT / 128), 256, SM_DD>>>(
        cath, CP, wa1, DP, b_a1, t1h, Hn, MT, Hn, DP, 0, 0, nullptr, nullptr, nullptr);
    hgemm<false, false, 1, true, false><<<dim3(Hn / 128, MT / 128), 256, SM_DD>>>(
        t1h, Hn, wa2, Hn, b_a2, fah, Hn, MT, Hn, Hn, 0, 0, nullptr, nullptr, nullptr);

    // (4,5) G1T = hemb^T @ fhR^T ; G2T = pemb^T @ fp (split-K 16, A trans from cath)
    hgemm<true, false, 0, false, true><<<dim3(4, 3, NSPL), 256, SM_TD>>>(
        cath + (size_t)LPn * CP, CP, fhR, LHn, nullptr, part, Hn,
        Dn, Hn, LHn, LHn / NSPL, DP, nullptr, nullptr, nullptr);
    hgemm<true, true, 0, false, true><<<dim3(4, 3, NSPL), 256, SM_TT>>>(
        cath, CP, fah, Hn, nullptr, part2, Hn,
        Dn, Hn, LPn, LPn / NSPL, DP, nullptr, nullptr, nullptr);

    // (6) merged reduce -> G1h, G2h
    reduce2_h<<<(2 * Dn * Hn / 4 + TB - 1) / TB, TB>>>(part, part2, G1h, G2h, Dn * Hn);

    // (7) E = fp @ fhR, trans-B, fused row/col sums
    hgemm<false, true, 3, false, false><<<dim3(LHn / 128, LPn / 128), 256, SM_DT>>>(
        fah, Hn, fhR, LHn, nullptr, outE, LHn, LPn, LHn, Hn, 0, 0, eik, ekj, nullptr);

    // (8) beta = diag(1/eik) * fp @ G1 -> outBeta + cath halves
    hgemm<false, false, 2, false, false><<<dim3(3, LPn / 128), 256, SM_DD>>>(
        fah, Hn, G1h, Hn, eik, outBeta, Dn, LPn, Dn, Hn, 0, 0, nullptr, nullptr, cath);

    // (9) alpha = diag(1/ekj) * fhR^T @ G2 -> outAlpha + cath halves
    hgemm<true, false, 2, false, false><<<dim3(3, LHn / 128), 256, SM_TD>>>(
        fhR, LHn, G2h, Hn, ekj, outAlpha, Dn, LHn, Dn, Hn, 0, LHn,
        nullptr, nullptr, cath + (size_t)LPn * CP);

    // (10,11) comp: cath -> t1h -> fused column sums into v
    hgemm<false, false, 1, true, false><<<dim3(Hn / 128, MT / 128), 256, SM_DD>>>(
        cath, CP, wc1, CP, b_c1, t1h, Hn, MT, Hn, CP, 0, 0, nullptr, nullptr, nullptr);
    hgemm<false, false, 4, false, false><<<dim3(Hn / 128, MT / 128), 256, SM_DD>>>(
        t1h, Hn, wc2, Hn, b_c2, nullptr, Hn, MT, Hn, Hn, 0, 0, v, nullptr, nullptr);

    // (12-14) parallel final head
    fin_k<<<Hn, 256>>>(W_g1, b_g1, v, y1, outV, 2 * Hn);
    fin_k<<<Hn, 256>>>(W_g2, b_g2, y1, y2, nullptr, Hn);
    fin3_k<<<1, 128>>>(W_g3, b_g3, y2, outY);
}